// round 15
// baseline (speedup 1.0000x reference)
#include <cuda_runtime.h>
#include <cuda_bf16.h>

// Shape: sequence_output [B=8, S=4096, H=1024] f32, sent_token_mask [B,S] int32.
// Output: concat f32 buffer [features (B*S*H) | segment_ids (B*S)].
//
// Evidence through R14:
//  - CE memcpy ~40us (~6.7 TB/s) is the best copy; CE-splitting is neutral.
//  - Event-based fork-join costs ~6us of graph overhead (R12/R14 vs R5 math).
//  - The 12.6us scan was single-SM LSU-bound (one block issuing 8192 LDG).
// This round: NO streams, NO events. Serial graph of 3 nodes:
//   [scan A: per-batch sums] -> [scan B: offsets + emit ids] -> [memcpy].
// Scan spread over B=8 blocks (one per batch) -> each kernel ~2us.
// Cross-kernel scratch in __device__ globals (allowed by harness rules).

#define MAX_B 32

__device__ int g_zc[MAX_B];   // zeros count per batch
__device__ int g_lf[MAX_B];   // last-label==1 flag per batch

// ---- Kernel A: per-batch zero counts + last-label flags --------------------
__global__ __launch_bounds__(1024)
void batch_sums_kernel(const int* __restrict__ labels, int S)
{
    const int b    = blockIdx.x;
    const int tid  = threadIdx.x;
    const int lane = tid & 31;
    const int wid  = tid >> 5;

    __shared__ int ws[32];

    // 1024 threads x 1 int4 = 4096 labels = one batch.
    const int4* lab4 = reinterpret_cast<const int4*>(labels + (long long)b * S);
    int4 q = lab4[tid];
    int s = (q.x == 0) + (q.y == 0) + (q.z == 0) + (q.w == 0);

    // Warp reduce.
    #pragma unroll
    for (int off = 16; off > 0; off >>= 1)
        s += __shfl_down_sync(0xFFFFFFFFu, s, off);
    if (lane == 0) ws[wid] = s;
    __syncthreads();

    // Warp 0 reduces the 32 warp sums (all lanes valid: 32 warps/block).
    if (wid == 0) {
        int v = ws[lane];
        #pragma unroll
        for (int off = 16; off > 0; off >>= 1)
            v += __shfl_down_sync(0xFFFFFFFFu, v, off);
        if (lane == 0) g_zc[b] = v;
    }
    if (tid == 0) g_lf[b] = (labels[(long long)b * S + S - 1] == 1);
}

// ---- Kernel B: per-batch base offsets + full scan + id emission ------------
__global__ __launch_bounds__(1024)
void emit_ids_kernel(const int* __restrict__ labels,
                     float* __restrict__ out_ids, int S)
{
    const int b    = blockIdx.x;
    const int tid  = threadIdx.x;
    const int lane = tid & 31;
    const int wid  = tid >> 5;

    __shared__ int ws[32];
    __shared__ int base_off;

    // 1024 threads x 1 int4 = one batch (labels now L2-hot from kernel A).
    const int4* lab4 = reinterpret_cast<const int4*>(labels + (long long)b * S);
    int4 q = lab4[tid];
    int s = (q.x == 0) + (q.y == 0) + (q.z == 0) + (q.w == 0);

    // Warp-level inclusive scan (all 32 lanes participate).
    int incl = s;
    #pragma unroll
    for (int off = 1; off < 32; off <<= 1) {
        int n = __shfl_up_sync(0xFFFFFFFFu, incl, off);
        if (lane >= off) incl += n;
    }
    if (lane == 31) ws[wid] = incl;

    // Warp 1: this block's base offset = sum over previous batches of
    // (zero count + last-label flag). Full-warp reduction.
    if (wid == 1) {
        int t = (lane < b) ? (g_zc[lane] + g_lf[lane]) : 0;
        #pragma unroll
        for (int off = 16; off > 0; off >>= 1)
            t += __shfl_down_sync(0xFFFFFFFFu, t, off);
        if (lane == 0) base_off = t;
    }
    __syncthreads();

    // Warp 0: full-warp exclusive scan over the 32 warp sums.
    if (wid == 0) {
        int v = ws[lane];
        int w = v;
        #pragma unroll
        for (int off = 1; off < 32; off <<= 1) {
            int n = __shfl_up_sync(0xFFFFFFFFu, w, off);
            if (lane >= off) w += n;
        }
        ws[lane] = w - v;                       // exclusive prefix
    }
    __syncthreads();

    int run = base_off + ws[wid] + (incl - s);

    // Emit 4 ids (id BEFORE increment) as one float4 store.
    float4 o;
    o.x = (float)run; run += (q.x == 0);
    o.y = (float)run; run += (q.y == 0);
    o.z = (float)run; run += (q.z == 0);
    o.w = (float)run; run += (q.w == 0);
    reinterpret_cast<float4*>(out_ids + (long long)b * S)[tid] = o;
}

extern "C" void kernel_launch(void* const* d_in, const int* in_sizes, int n_in,
                              void* d_out, int out_size)
{
    const float* seq    = (const float*)d_in[0];
    const int*   labels = (const int*)d_in[1];
    float*       out    = (float*)d_out;

    const long long n_feat = in_sizes[0];   // B*S*H = 33,554,432
    const int       n_tok  = in_sizes[1];   // B*S   = 32,768
    const int       S      = 4096;
    const int       B      = n_tok / S;     // 8

    // Serial 3-node graph on the capture stream: tiny scans (~4us total),
    // then the CE SOL copy (~40us). No streams/events (saves ~6us of
    // fork-join overhead measured in R12/R14).
    batch_sums_kernel<<<B, 1024>>>(labels, S);
    emit_ids_kernel<<<B, 1024>>>(labels, out + n_feat, S);
    cudaMemcpyAsync(out, seq, (size_t)n_feat * sizeof(float),
                    cudaMemcpyDeviceToDevice, 0);
}

// round 16
// speedup vs baseline: 1.0908x; 1.0908x over previous
#include <cuda_runtime.h>
#include <cuda_bf16.h>

// Shape: sequence_output [B=8, S=4096, H=1024] f32, sent_token_mask [B,S] int32.
// Output: concat f32 buffer [features (B*S*H) | segment_ids (B*S)].
//
// Hypothesis under test: the ~6.7 TB/s memcpy ceiling is a COPY-ENGINE limit,
// not the DRAM r+w ceiling. So run CE and SM copy paths CONCURRENTLY on
// disjoint ranges:
//   stream 0 : CE memcpy of features[0 .. 5/8)
//   stream s2: fused SM kernel -- block 0 = segment-id scan (R11-proven,
//              register-capped), blocks 1..591 = dense wave-sweep copy of
//              features[5/8 .. 1)   (~4.7-5 TB/s on this path)
// Join via e_join. Object budget identical to R12/R14 (1 stream + 2 events,
// passes the allocation guard).

#define THREADS      512
#define COPY_BLOCKS  591       // +1 scan block = 592 = 148*4, one wave
#define MAX_B 32

__global__ __launch_bounds__(THREADS, 4)
void sm_copy_scan_kernel(const float4* __restrict__ src,
                         float4* __restrict__ dst,
                         long long start4, long long n4,
                         const int* __restrict__ labels,
                         float* __restrict__ out_ids,
                         int B, int S, int n_tok)
{
    if (blockIdx.x == 0) {
        // ---------------- segment-id scan (one 512-thread block) ----------
        __shared__ int warp_sums[32];               // padded to full warp
        __shared__ int extra_off[MAX_B];

        const int tid  = threadIdx.x;
        const int lane = tid & 31;
        const int wid  = tid >> 5;                  // 0..15
        const int per  = n_tok / THREADS;           // 64 for this shape
        const int base = tid * per;

        if (tid < 32) warp_sums[tid] = 0;

        const int4* lab4 = reinterpret_cast<const int4*>(labels + base);
        int s = 0;
        #pragma unroll
        for (int v = 0; v < 16; v++) {
            int4 q = lab4[v];
            s += (q.x == 0) + (q.y == 0) + (q.z == 0) + (q.w == 0);
        }

        // Warp-level inclusive scan (all 32 lanes participate).
        int incl = s;
        #pragma unroll
        for (int off = 1; off < 32; off <<= 1) {
            int n = __shfl_up_sync(0xFFFFFFFFu, incl, off);
            if (lane >= off) incl += n;
        }

        // Warp 1: per-batch "extra" exclusive offsets (full-warp shuffles).
        if (wid == 1) {
            int flag = (lane < B) ? (labels[lane * S + S - 1] == 1) : 0;
            int e = flag;
            #pragma unroll
            for (int off = 1; off < 32; off <<= 1) {
                int n = __shfl_up_sync(0xFFFFFFFFu, e, off);
                if (lane >= off) e += n;
            }
            extra_off[lane] = e - flag;             // exclusive
        }
        __syncthreads();

        if (lane == 31) warp_sums[wid] = incl;
        __syncthreads();

        // Warp 0: full-warp exclusive scan over 32 (16 real + 16 zero) sums.
        if (wid == 0) {
            int v = warp_sums[lane];
            int w = v;
            #pragma unroll
            for (int off = 1; off < 32; off <<= 1) {
                int n = __shfl_up_sync(0xFFFFFFFFu, w, off);
                if (lane >= off) w += n;
            }
            warp_sums[lane] = w - v;
        }
        __syncthreads();

        // per (=64) divides S (=4096): each thread stays within one batch.
        int run = warp_sums[wid] + (incl - s) + extra_off[base / S];

        float4* out4 = reinterpret_cast<float4*>(out_ids + base);
        #pragma unroll
        for (int v = 0; v < 16; v++) {
            int4 q = lab4[v];
            float4 o;
            o.x = (float)run; run += (q.x == 0);
            o.y = (float)run; run += (q.y == 0);
            o.z = (float)run; run += (q.z == 0);
            o.w = (float)run; run += (q.w == 0);
            out4[v] = o;
        }
    } else {
        // ---------------- SM copy of [start4, n4) -------------------------
        // Dense wave sweep (best SM pattern), 64 warps/SM via the reg cap.
        const long long T = (long long)COPY_BLOCKS * THREADS;   // 302,592
        long long i = start4 + (long long)(blockIdx.x - 1) * THREADS + threadIdx.x;
        for (; i < n4; i += T) {
            dst[i] = src[i];
        }
    }
}

extern "C" void kernel_launch(void* const* d_in, const int* in_sizes, int n_in,
                              void* d_out, int out_size)
{
    const float* seq    = (const float*)d_in[0];
    const int*   labels = (const int*)d_in[1];
    float*       out    = (float*)d_out;

    const long long n_feat = in_sizes[0];   // B*S*H = 33,554,432
    const int       n_tok  = in_sizes[1];   // B*S   = 32,768
    const int       S      = 4096;
    const int       B      = n_tok / S;

    const long long n4 = n_feat / 4;        // 8,388,608 float4

    // Host-side objects, created once -- exactly R12/R14's guard-passing set.
    static cudaStream_t s2 = nullptr;
    static cudaEvent_t  e_fork = nullptr, e_join = nullptr;
    static bool         tried = false;
    if (!tried) {
        tried = true;
        if (cudaStreamCreateWithFlags(&s2, cudaStreamNonBlocking) != cudaSuccess)
            s2 = nullptr;
        if (s2) {
            if (cudaEventCreateWithFlags(&e_fork, cudaEventDisableTiming) != cudaSuccess ||
                cudaEventCreateWithFlags(&e_join, cudaEventDisableTiming) != cudaSuccess) {
                s2 = nullptr;
            }
        }
    }

    if (s2) {
        // CE takes the first 5/8; the SM kernel takes the last 3/8 + scan.
        const size_t    c0     = (size_t)(n_feat / 8) * 5;   // floats, /4 ok
        const long long start4 = (long long)c0 / 4;

        cudaEventRecord(e_fork, 0);
        cudaStreamWaitEvent(s2, e_fork, 0);

        sm_copy_scan_kernel<<<COPY_BLOCKS + 1, THREADS, 0, s2>>>(
            (const float4*)seq, (float4*)out, start4, n4,
            labels, out + n_feat, B, S, n_tok);
        cudaEventRecord(e_join, s2);

        cudaMemcpyAsync(out, seq, c0 * sizeof(float),
                        cudaMemcpyDeviceToDevice, 0);
        cudaStreamWaitEvent(0, e_join, 0);
    } else {
        // Fallback: serialized, SM kernel covers the whole range.
        sm_copy_scan_kernel<<<COPY_BLOCKS + 1, THREADS>>>(
            (const float4*)seq, (float4*)out, 0, n4,
            labels, out + n_feat, B, S, n_tok);
    }
}